// round 9
// baseline (speedup 1.0000x reference)
#include <cuda_runtime.h>
#include <cuda_bf16.h>
#include <math.h>
#include <stdint.h>

#define DIMC 128
#define NMAX 50000
#define MMAX 2500
#define CAP  2048
#define MAXK 32
#define KNN  8
#define SCALE 0.17677669529663687f  // 1/sqrt(32)

// spatial grid
#define GC   28
#define NCELL (GC*GC*GC)          // 21952
#define CELLH 0.45f
#define INVH  2.2222222222222223f
#define ORG  (-6.3f)

// ---------------- scratch (__device__ globals; no allocation allowed) -------
__device__ float4 g_center[MMAX];
__device__ int    g_ccell[MMAX];
__device__ int    g_ccnt[MMAX];
__device__ float  g_cfeat[MMAX * DIMC];
__device__ int    g_cand_idx[MMAX * CAP];
__device__ float  g_cand_dist[MMAX * CAP];
__device__ int    g_nbr_idx[MMAX * MAXK];
__device__ int    g_nbr_cnt[MMAX];
__device__ float  g_q[MMAX * DIMC];
__device__ float  g_attnout[MMAX * DIMC];
__device__ float  g_upd[MMAX * DIMC];
__device__ float  g_cf1[MMAX * DIMC];
__device__ float  g_hid[MMAX * 4 * DIMC];
__device__ float  g_ffn[MMAX * DIMC];
__device__ float  g_cf[MMAX * DIMC];
__device__ float  g_kall[NMAX * DIMC];   // later reused as U (interp output)
__device__ float  g_vall[NMAX * DIMC];
__device__ int    g_knn_idx[NMAX * KNN];
__device__ float  g_knn_dist[NMAX * KNN];
// center binning
__device__ int    g_cellcnt[NCELL];
__device__ int    g_cellstart[NCELL + 1];
__device__ int    g_cellptr[NCELL];
__device__ float4 g_binc[MMAX];
__device__ int    g_binm[MMAX];
// point sorting
__device__ int    g_pcellcnt[NCELL];
__device__ int    g_pcellstart[NCELL + 1];
__device__ int    g_pcellptr[NCELL];
__device__ float4 g_pxyz[NMAX];
__device__ int    g_psort[NMAX];

// ---------------- f32x2 packed-FMA helpers ----------------------------------
__device__ __forceinline__ void fma2(unsigned long long& d, unsigned long long a,
                                     unsigned long long b) {
    asm("fma.rn.f32x2 %0, %1, %2, %0;" : "+l"(d) : "l"(a), "l"(b));
}
__device__ __forceinline__ unsigned long long pack2(float v) {
    unsigned long long r;
    asm("mov.b64 %0, {%1, %1};" : "=l"(r) : "r"(__float_as_uint(v)));
    return r;
}
__device__ __forceinline__ float2 unpack2(unsigned long long a) {
    unsigned int lo, hi;
    asm("mov.b64 {%0, %1}, %2;" : "=r"(lo), "=r"(hi) : "l"(a));
    return make_float2(__uint_as_float(lo), __uint_as_float(hi));
}

// ---------------- mma.sync helpers (baseline PTX, sm_80+) --------------------
__device__ __forceinline__ uint32_t smem_u32(const void* p) {
    uint32_t a;
    asm("{ .reg .u64 t; cvta.to.shared.u64 t, %1; cvt.u32.u64 %0, t; }" : "=r"(a) : "l"(p));
    return a;
}
__device__ __forceinline__ void ldsm4(uint32_t* r, uint32_t addr) {
    asm volatile("ldmatrix.sync.aligned.m8n8.x4.shared.b16 {%0,%1,%2,%3}, [%4];"
                 : "=r"(r[0]), "=r"(r[1]), "=r"(r[2]), "=r"(r[3]) : "r"(addr));
}
__device__ __forceinline__ void ldsm4t(uint32_t* r, uint32_t addr) {
    asm volatile("ldmatrix.sync.aligned.m8n8.x4.trans.shared.b16 {%0,%1,%2,%3}, [%4];"
                 : "=r"(r[0]), "=r"(r[1]), "=r"(r[2]), "=r"(r[3]) : "r"(addr));
}
__device__ __forceinline__ void mma16816(float* c, const uint32_t* a, const uint32_t* b) {
    asm volatile(
        "mma.sync.aligned.m16n8k16.row.col.f32.bf16.bf16.f32 "
        "{%0,%1,%2,%3}, {%4,%5,%6,%7}, {%8,%9}, {%0,%1,%2,%3};"
        : "+f"(c[0]), "+f"(c[1]), "+f"(c[2]), "+f"(c[3])
        : "r"(a[0]), "r"(a[1]), "r"(a[2]), "r"(a[3]), "r"(b[0]), "r"(b[1]));
}

// ============================================================================
// bf16-split tensor GEMM: C[Mr x 128] = A[Mr x 128] @ W[128 x 128]
// 3-term: Ahi*Bhi + Ahi*Blo + Alo*Bhi, fp32 accumulate.
// EPI 0: C = acc        EPI 1: C = F + A + relu(acc + bias)   (fused upsample)
// ============================================================================
#define TLD 136                      // smem row stride (bf16 elems), conflict-free
#define TG_SMEM_BYTES (4 * 128 * TLD * 2)

template <int EPI>
__global__ __launch_bounds__(256, 1) void tgemm_kernel(
    const float* __restrict__ A, const float* __restrict__ W,
    const float* __restrict__ bias, float* __restrict__ C,
    const float* __restrict__ F, int Mr) {
    extern __shared__ __nv_bfloat16 sm[];
    __nv_bfloat16* Ahi = sm;
    __nv_bfloat16* Alo = sm + 128 * TLD;
    __nv_bfloat16* Bhi = sm + 2 * 128 * TLD;
    __nv_bfloat16* Blo = sm + 3 * 128 * TLD;

    int tid = threadIdx.x;           // 256 threads = 8 warps
    int bm = blockIdx.x * 128;

    // W[k][n] -> Bhi/Blo (row-major [k][n], ldmatrix.trans consumes as col-major B)
    for (int i = tid; i < 16384; i += 256) {
        int k = i >> 7, n = i & 127;
        float v = W[i];
        __nv_bfloat16 h = __float2bfloat16(v);
        __nv_bfloat16 l = __float2bfloat16(v - __bfloat162float(h));
        Bhi[k * TLD + n] = h;
        Blo[k * TLD + n] = l;
    }
    // A rows -> Ahi/Alo
    for (int i = tid; i < 16384; i += 256) {
        int r = i >> 7, c = i & 127;
        int row = bm + r;
        float v = (row < Mr) ? A[(size_t)row * DIMC + c] : 0.0f;
        __nv_bfloat16 h = __float2bfloat16(v);
        __nv_bfloat16 l = __float2bfloat16(v - __bfloat162float(h));
        Ahi[r * TLD + c] = h;
        Alo[r * TLD + c] = l;
    }
    __syncthreads();

    int w = tid >> 5, lane = tid & 31;
    int wr = w >> 1, wc = w & 1;     // warp covers rows [wr*32, +32), cols [wc*64, +64)

    float acc[2][8][4];
#pragma unroll
    for (int mt = 0; mt < 2; mt++)
#pragma unroll
        for (int j = 0; j < 8; j++)
#pragma unroll
            for (int e = 0; e < 4; e++) acc[mt][j][e] = 0.0f;

    uint32_t aBaseHi = smem_u32(Ahi), aBaseLo = smem_u32(Alo);
    uint32_t bBaseHi = smem_u32(Bhi), bBaseLo = smem_u32(Blo);
    int arow = wr * 32 + (lane & 15);
    int acolq = (lane >> 4) * 8;
    int brow = lane & 15;
    int bcolq = wc * 64 + (lane >> 4) * 8;

#pragma unroll
    for (int ks = 0; ks < 8; ks++) {
        int k0 = ks * 16;
        uint32_t ahi[2][4], alo[2][4];
#pragma unroll
        for (int mt = 0; mt < 2; mt++) {
            uint32_t off = (uint32_t)((arow + mt * 16) * TLD + k0 + acolq) * 2;
            ldsm4(ahi[mt], aBaseHi + off);
            ldsm4(alo[mt], aBaseLo + off);
        }
#pragma unroll
        for (int nb = 0; nb < 4; nb++) {
            uint32_t boff = (uint32_t)((k0 + brow) * TLD + bcolq + nb * 16) * 2;
            uint32_t bh[4], bl[4];
            ldsm4t(bh, bBaseHi + boff);
            ldsm4t(bl, bBaseLo + boff);
#pragma unroll
            for (int mt = 0; mt < 2; mt++) {
                mma16816(acc[mt][2 * nb + 0], ahi[mt], bh + 0);
                mma16816(acc[mt][2 * nb + 1], ahi[mt], bh + 2);
                mma16816(acc[mt][2 * nb + 0], ahi[mt], bl + 0);
                mma16816(acc[mt][2 * nb + 1], ahi[mt], bl + 2);
                mma16816(acc[mt][2 * nb + 0], alo[mt], bh + 0);
                mma16816(acc[mt][2 * nb + 1], alo[mt], bh + 2);
            }
        }
    }

    // epilogue: fragment rows (lane>>2) and (lane>>2)+8, cols (lane&3)*2
#pragma unroll
    for (int mt = 0; mt < 2; mt++) {
        int r0 = bm + wr * 32 + mt * 16 + (lane >> 2);
#pragma unroll
        for (int j = 0; j < 8; j++) {
            int c = wc * 64 + j * 8 + (lane & 3) * 2;
#pragma unroll
            for (int half = 0; half < 2; half++) {
                int row = r0 + half * 8;
                if (row < Mr) {
                    float vx = acc[mt][j][2 * half + 0];
                    float vy = acc[mt][j][2 * half + 1];
                    if (EPI == 1) {
                        vx = fmaxf(vx + bias[c + 0], 0.f);
                        vy = fmaxf(vy + bias[c + 1], 0.f);
                        const float* fr = &F[(size_t)row * DIMC + c];
                        const float* ur = &A[(size_t)row * DIMC + c];
                        vx += fr[0] + ur[0];
                        vy += fr[1] + ur[1];
                    }
                    float2 v2 = make_float2(vx, vy);
                    *(float2*)&C[(size_t)row * DIMC + c] = v2;
                }
            }
        }
    }
}

// ---------------- gather centers + zero counters ----------------------------
__global__ void gather_kernel(const float* __restrict__ xyz,
                              const float* __restrict__ feats,
                              const int* __restrict__ idxc, int M) {
    int t = blockIdx.x * blockDim.x + threadIdx.x;
    if (t < M) {
        int n = idxc[t];
        float x = xyz[n * 3 + 0], y = xyz[n * 3 + 1], z = xyz[n * 3 + 2];
        g_center[t] = make_float4(x, y, z, x * x + y * y + z * z);
        g_ccnt[t] = 0;
        int ix = min(max((int)floorf((x - ORG) * INVH), 0), GC - 1);
        int iy = min(max((int)floorf((y - ORG) * INVH), 0), GC - 1);
        int iz = min(max((int)floorf((z - ORG) * INVH), 0), GC - 1);
        g_ccell[t] = (iz * GC + iy) * GC + ix;
    }
    if (t < M * DIMC) {
        int m = t >> 7, c = t & 127;
        g_cfeat[t] = feats[idxc[m] * DIMC + c];
    }
}

// ---------------- binning: count / scan / scatter ---------------------------
__global__ void bin_count_kernel(int M) {
    int m = blockIdx.x * blockDim.x + threadIdx.x;
    if (m < M) atomicAdd(&g_cellcnt[g_ccell[m]], 1);
}

__global__ void scan_cells_kernel(const int* __restrict__ cnt, int* __restrict__ start,
                                  int* __restrict__ ptr, int ncell) {
    __shared__ int part[1024];
    int t = threadIdx.x;
    int PER = (ncell + 1023) / 1024;
    int b0 = t * PER, b1 = min(b0 + PER, ncell);
    int s = 0;
    for (int i = b0; i < b1; i++) s += cnt[i];
    part[t] = s;
    __syncthreads();
    for (int off = 1; off < 1024; off <<= 1) {
        int v = (t >= off) ? part[t - off] : 0;
        __syncthreads();
        part[t] += v;
        __syncthreads();
    }
    int run = (t == 0) ? 0 : part[t - 1];
    for (int i = b0; i < b1; i++) {
        int c = cnt[i];
        start[i] = run;
        ptr[i] = run;
        run += c;
    }
    if (t == 1023) start[ncell] = run;
}

__global__ void bin_scatter_kernel(int M) {
    int m = blockIdx.x * blockDim.x + threadIdx.x;
    if (m < M) {
        int slot = atomicAdd(&g_cellptr[g_ccell[m]], 1);
        g_binc[slot] = g_center[m];
        g_binm[slot] = m;
    }
}

// ---------------- point sort by cell ----------------------------------------
__global__ void point_cell_kernel(const float* __restrict__ xyz, int N) {
    int n = blockIdx.x * blockDim.x + threadIdx.x;
    if (n >= N) return;
    float x = xyz[n * 3 + 0], y = xyz[n * 3 + 1], z = xyz[n * 3 + 2];
    int ix = min(max((int)floorf((x - ORG) * INVH), 0), GC - 1);
    int iy = min(max((int)floorf((y - ORG) * INVH), 0), GC - 1);
    int iz = min(max((int)floorf((z - ORG) * INVH), 0), GC - 1);
    atomicAdd(&g_pcellcnt[(iz * GC + iy) * GC + ix], 1);
}

__global__ void point_scatter_kernel(const float* __restrict__ xyz, int N) {
    int n = blockIdx.x * blockDim.x + threadIdx.x;
    if (n >= N) return;
    float x = xyz[n * 3 + 0], y = xyz[n * 3 + 1], z = xyz[n * 3 + 2];
    int ix = min(max((int)floorf((x - ORG) * INVH), 0), GC - 1);
    int iy = min(max((int)floorf((y - ORG) * INVH), 0), GC - 1);
    int iz = min(max((int)floorf((z - ORG) * INVH), 0), GC - 1);
    int slot = atomicAdd(&g_pcellptr[(iz * GC + iy) * GC + ix], 1);
    g_pxyz[slot] = make_float4(x, y, z, x * x + y * y + z * z);
    g_psort[slot] = n;
}

// ---------------- per-cell scan helper ---------------------------------------
template <bool BALL>
__device__ __forceinline__ void scan_cell(int cid, float x, float y, float z, float s,
                                          int n, float kd[KNN], int ki[KNN]) {
    int c0 = g_cellstart[cid], c1 = g_cellstart[cid + 1];
    for (int j = c0; j < c1; j++) {
        float4 c = g_binc[j];
        float dot = c.x * x + c.y * y + c.z * z;
        float d2 = (c.w + s) - 2.0f * dot;
        if (BALL) {
            if (d2 < 0.0900001f) {
                float dist = (d2 > 0.0f) ? sqrtf(d2) : 0.0f;
                if (dist < 0.3f) {
                    int m = g_binm[j];
                    int slot = atomicAdd(&g_ccnt[m], 1);
                    if (slot < CAP) {
                        g_cand_idx[m * CAP + slot] = n;
                        g_cand_dist[m * CAP + slot] = dist;
                    }
                }
            }
        }
        if (d2 < kd[KNN - 1]) {
            float nd = d2;
            int ni = g_binm[j];
#pragma unroll
            for (int i = 0; i < KNN; i++) {
                if (nd < kd[i]) {
                    float td = kd[i]; int ti = ki[i];
                    kd[i] = nd; ki[i] = ni; nd = td; ni = ti;
                }
            }
        }
    }
}

// ---------------- point scan over SORTED points: ball + exact KNN -----------
__global__ void point_scan_kernel(int N) {
    int t = blockIdx.x * blockDim.x + threadIdx.x;
    if (t >= N) return;
    float4 p = g_pxyz[t];
    int n = g_psort[t];
    float x = p.x, y = p.y, z = p.z, s = p.w;
    int ix = min(max((int)floorf((x - ORG) * INVH), 0), GC - 1);
    int iy = min(max((int)floorf((y - ORG) * INVH), 0), GC - 1);
    int iz = min(max((int)floorf((z - ORG) * INVH), 0), GC - 1);

    float kd[KNN]; int ki[KNN];
#pragma unroll
    for (int i = 0; i < KNN; i++) { kd[i] = 3.0e38f; ki[i] = -1; }

    for (int dz = -1; dz <= 1; dz++) {
        int jz = iz + dz; if (jz < 0 || jz >= GC) continue;
        for (int dy = -1; dy <= 1; dy++) {
            int jy = iy + dy; if (jy < 0 || jy >= GC) continue;
            for (int dx = -1; dx <= 1; dx++) {
                int jx = ix + dx; if (jx < 0 || jx >= GC) continue;
                scan_cell<true>((jz * GC + jy) * GC + jx, x, y, z, s, n, kd, ki);
            }
        }
    }
    int R = 1;
    while (true) {
        float rx = fminf(x - (ORG + (ix - R) * CELLH), (ORG + (ix + R + 1) * CELLH) - x);
        float ry = fminf(y - (ORG + (iy - R) * CELLH), (ORG + (iy + R + 1) * CELLH) - y);
        float rz = fminf(z - (ORG + (iz - R) * CELLH), (ORG + (iz + R + 1) * CELLH) - z);
        float rc = fminf(rx, fminf(ry, rz));
        if (rc > 0.0f && kd[KNN - 1] < rc * rc) break;
        if (R >= GC) break;
        R++;
        for (int dz = -R; dz <= R; dz++) {
            int jz = iz + dz; if (jz < 0 || jz >= GC) continue;
            bool zf = (dz == -R) || (dz == R);
            for (int dy = -R; dy <= R; dy++) {
                int jy = iy + dy; if (jy < 0 || jy >= GC) continue;
                bool yf = (dy == -R) || (dy == R);
                if (zf || yf) {
                    for (int dx = -R; dx <= R; dx++) {
                        int jx = ix + dx; if (jx < 0 || jx >= GC) continue;
                        scan_cell<false>((jz * GC + jy) * GC + jx, x, y, z, s, n, kd, ki);
                    }
                } else {
                    int jx = ix - R;
                    if (jx >= 0) scan_cell<false>((jz * GC + jy) * GC + jx, x, y, z, s, n, kd, ki);
                    jx = ix + R;
                    if (jx < GC) scan_cell<false>((jz * GC + jy) * GC + jx, x, y, z, s, n, kd, ki);
                }
            }
        }
    }
#pragma unroll
    for (int i = 0; i < KNN; i++) {
        float d2 = kd[i];
        g_knn_idx[n * KNN + i] = ki[i];
        g_knn_dist[n * KNN + i] = (d2 > 0.0f) ? sqrtf(d2) : 0.0f;
    }
}

// ---------------- per-center top-32 selection (stable ties by index) --------
__global__ void select_topk_kernel(int M) {
    int m = blockIdx.x;
    int tid = threadIdx.x;  // 128
    __shared__ float sd[CAP];
    __shared__ int   si[CAP];
    __shared__ float rd[128];
    __shared__ int   ri[128];
    __shared__ int   rp[128];
    int cnt = g_ccnt[m];
    if (cnt > CAP) cnt = CAP;
    for (int i = tid; i < cnt; i += blockDim.x) {
        sd[i] = g_cand_dist[m * CAP + i];
        si[i] = g_cand_idx[m * CAP + i];
    }
    __syncthreads();
    for (int r = 0; r < MAXK; r++) {
        float bd = 3.0e38f; int bi = 0x7fffffff; int bp = -1;
        for (int i = tid; i < cnt; i += blockDim.x) {
            float dd = sd[i]; int ii = si[i];
            if (dd < bd || (dd == bd && ii < bi)) { bd = dd; bi = ii; bp = i; }
        }
        rd[tid] = bd; ri[tid] = bi; rp[tid] = bp;
        __syncthreads();
        for (int st = 64; st > 0; st >>= 1) {
            if (tid < st) {
                if (rd[tid + st] < rd[tid] ||
                    (rd[tid + st] == rd[tid] && ri[tid + st] < ri[tid])) {
                    rd[tid] = rd[tid + st]; ri[tid] = ri[tid + st]; rp[tid] = rp[tid + st];
                }
            }
            __syncthreads();
        }
        if (tid == 0) {
            g_nbr_idx[m * MAXK + r] = (r < cnt) ? ri[0] : -1;
            if (rp[0] >= 0) sd[rp[0]] = 3.0e38f;
        }
        __syncthreads();
    }
    if (tid == 0) g_nbr_cnt[m] = (cnt < MAXK) ? cnt : MAXK;
}

// ---------------- fp32 tiled GEMM 32x128 tile (small M, exact fp32) ---------
template <bool BIAS, bool RELU>
__global__ void gemm32_kernel(const float* __restrict__ A, const float* __restrict__ B,
                              const float* __restrict__ bias, float* __restrict__ C,
                              int Mr, int K, int Nc) {
    __shared__ float As[8][33];
    __shared__ float Bs[8][128];
    int bm = blockIdx.x * 32;
    int bn = blockIdx.y * 128;
    int tid = threadIdx.x;
    int ty = tid >> 5, tx = tid & 31;
    unsigned long long acc2[4][2];
#pragma unroll
    for (int i = 0; i < 4; i++) { acc2[i][0] = 0ull; acc2[i][1] = 0ull; }

    int arow = tid >> 3, acol = tid & 7;
    int brow = tid >> 5, bcol = (tid & 31) * 4;

    for (int k0 = 0; k0 < K; k0 += 8) {
        float av = 0.f;
        if (bm + arow < Mr) av = A[(size_t)(bm + arow) * K + k0 + acol];
        As[acol][arow] = av;
        *(float4*)&Bs[brow][bcol] = *(const float4*)&B[(size_t)(k0 + brow) * Nc + bn + bcol];
        __syncthreads();
#pragma unroll
        for (int kk = 0; kk < 8; kk++) {
            ulonglong2 bq = *(const ulonglong2*)&Bs[kk][tx * 4];
#pragma unroll
            for (int i = 0; i < 4; i++) {
                unsigned long long ai = pack2(As[kk][ty * 4 + i]);
                fma2(acc2[i][0], ai, bq.x);
                fma2(acc2[i][1], ai, bq.y);
            }
        }
        __syncthreads();
    }
#pragma unroll
    for (int i = 0; i < 4; i++) {
        int r = bm + ty * 4 + i;
        if (r < Mr) {
            int c = bn + tx * 4;
            float2 v0 = unpack2(acc2[i][0]);
            float2 v1 = unpack2(acc2[i][1]);
            float4 v = make_float4(v0.x, v0.y, v1.x, v1.y);
            if (BIAS) { v.x += bias[c]; v.y += bias[c + 1]; v.z += bias[c + 2]; v.w += bias[c + 3]; }
            if (RELU) {
                v.x = fmaxf(v.x, 0.f); v.y = fmaxf(v.y, 0.f);
                v.z = fmaxf(v.z, 0.f); v.w = fmaxf(v.w, 0.f);
            }
            *(float4*)&C[(size_t)r * Nc + c] = v;
        }
    }
}

// ---------------- per-center masked attention -------------------------------
__global__ void attn_kernel(int M) {
    int m = blockIdx.x;
    int t = threadIdx.x;  // 128 threads
    __shared__ float kb[MAXK * 129];
    __shared__ float vb[MAXK * 129];
    __shared__ float qs[128];
    __shared__ float at[128];
    __shared__ int   sidx[MAXK];
    int cnt = g_nbr_cnt[m];
    if (t < MAXK) sidx[t] = g_nbr_idx[m * MAXK + t];
    qs[t] = g_q[m * DIMC + t] * SCALE;
    __syncthreads();
    for (int j = 0; j < cnt; j++) {
        int idx = sidx[j];
        kb[j * 129 + t] = g_kall[(size_t)idx * DIMC + t];
        vb[j * 129 + t] = g_vall[(size_t)idx * DIMC + t];
    }
    __syncthreads();
    int h = t >> 5, j = t & 31;
    float sc;
    if (j < cnt) {
        const float* kr = &kb[j * 129 + h * 32];
        const float* qq = &qs[h * 32];
        float s = 0.f;
#pragma unroll
        for (int d = 0; d < 32; d++) s += qq[d] * kr[d];
        sc = s;
    } else {
        sc = -1e9f;
    }
    float mx = sc;
#pragma unroll
    for (int o = 16; o; o >>= 1) mx = fmaxf(mx, __shfl_xor_sync(0xffffffffu, mx, o));
    float e = expf(sc - mx);
    float sm = e;
#pragma unroll
    for (int o = 16; o; o >>= 1) sm += __shfl_xor_sync(0xffffffffu, sm, o);
    at[t] = e / sm;
    __syncthreads();
    int h2 = t & 3, d2 = t >> 2;
    float o = 0.f;
    for (int jj = 0; jj < cnt; jj++) o += at[h2 * 32 + jj] * vb[jj * 129 + h2 * 32 + d2];
    g_attnout[m * DIMC + t] = o;
}

// ---------------- LayerNorm + residual --------------------------------------
__global__ void ln_res_kernel(const float* __restrict__ x, const float* __restrict__ resid,
                              const float* __restrict__ w, const float* __restrict__ b,
                              float* __restrict__ out, int Mr) {
    int row = blockIdx.x * 8 + (threadIdx.x >> 5);
    int lane = threadIdx.x & 31;
    if (row >= Mr) return;
    const float* xr = x + (size_t)row * DIMC;
    float v[4];
#pragma unroll
    for (int i = 0; i < 4; i++) v[i] = xr[lane + 32 * i];
    float s = v[0] + v[1] + v[2] + v[3];
#pragma unroll
    for (int o = 16; o; o >>= 1) s += __shfl_xor_sync(0xffffffffu, s, o);
    float mu = s * 0.0078125f;
    float s2 = 0.f;
#pragma unroll
    for (int i = 0; i < 4; i++) { float d = v[i] - mu; s2 += d * d; }
#pragma unroll
    for (int o = 16; o; o >>= 1) s2 += __shfl_xor_sync(0xffffffffu, s2, o);
    float r = rsqrtf(s2 * 0.0078125f + 1e-5f);
    const float* rr = resid + (size_t)row * DIMC;
    float* orow = out + (size_t)row * DIMC;
#pragma unroll
    for (int i = 0; i < 4; i++) {
        int c = lane + 32 * i;
        orow[c] = rr[c] + (v[i] - mu) * r * w[c] + b[c];
    }
}

// ---------------- KNN inverse-distance interpolation ------------------------
__global__ void interp_kernel(float* __restrict__ U, int N) {
    int gt = blockIdx.x * blockDim.x + threadIdx.x;
    int p = gt >> 5, lane = gt & 31;
    if (p >= N) return;
    float w[KNN]; int id[KNN];
    float wsum = 0.f;
#pragma unroll
    for (int k = 0; k < KNN; k++) {
        id[k] = g_knn_idx[p * KNN + k];
        float d = g_knn_dist[p * KNN + k] + 1e-6f;
        w[k] = 1.0f / (d * d);
        wsum += w[k];
    }
    float inv = 1.0f / wsum;
    float4 acc = make_float4(0.f, 0.f, 0.f, 0.f);
#pragma unroll
    for (int k = 0; k < KNN; k++) {
        float4 v = *(const float4*)&g_cf[(size_t)id[k] * DIMC + lane * 4];
        acc.x += w[k] * v.x; acc.y += w[k] * v.y;
        acc.z += w[k] * v.z; acc.w += w[k] * v.w;
    }
    acc.x *= inv; acc.y *= inv; acc.z *= inv; acc.w *= inv;
    *(float4*)&U[(size_t)p * DIMC + lane * 4] = acc;
}

// ---------------- host launch ------------------------------------------------
static float* symf(const void* sym) { void* p = nullptr; cudaGetSymbolAddress(&p, sym); return (float*)p; }
static int*   symi(const void* sym) { void* p = nullptr; cudaGetSymbolAddress(&p, sym); return (int*)p; }

extern "C" void kernel_launch(void* const* d_in, const int* in_sizes, int n_in,
                              void* d_out, int out_size) {
    const float* xyz  = (const float*)d_in[0];
    const float* feats= (const float*)d_in[1];
    const float* Wq   = (const float*)d_in[2];
    const float* Wk   = (const float*)d_in[3];
    const float* Wv   = (const float*)d_in[4];
    const float* Wo   = (const float*)d_in[5];
    const float* bo   = (const float*)d_in[6];
    const float* n1w  = (const float*)d_in[7];
    const float* n1b  = (const float*)d_in[8];
    const float* n2w  = (const float*)d_in[9];
    const float* n2b  = (const float*)d_in[10];
    const float* W1   = (const float*)d_in[11];
    const float* b1   = (const float*)d_in[12];
    const float* W2   = (const float*)d_in[13];
    const float* b2   = (const float*)d_in[14];
    const float* Wp   = (const float*)d_in[15];
    const float* bp   = (const float*)d_in[16];
    const int* idxc   = (const int*)d_in[17];
    float* out = (float*)d_out;

    int N = in_sizes[0] / 3;
    int M = in_sizes[17];

    float* p_cfeat = symf(g_cfeat);
    float* p_q     = symf(g_q);
    float* p_kall  = symf(g_kall);
    float* p_vall  = symf(g_vall);
    float* p_ao    = symf(g_attnout);
    float* p_upd   = symf(g_upd);
    float* p_cf1   = symf(g_cf1);
    float* p_hid   = symf(g_hid);
    float* p_ffn   = symf(g_ffn);
    float* p_cf    = symf(g_cf);
    int*   p_ccnt  = symi(g_cellcnt);
    int*   p_cstart= symi(g_cellstart);
    int*   p_cptr  = symi(g_cellptr);
    int*   p_pcnt  = symi(g_pcellcnt);
    int*   p_pstart= symi(g_pcellstart);
    int*   p_pptr  = symi(g_pcellptr);

    cudaFuncSetAttribute(tgemm_kernel<0>, cudaFuncAttributeMaxDynamicSharedMemorySize, TG_SMEM_BYTES);
    cudaFuncSetAttribute(tgemm_kernel<1>, cudaFuncAttributeMaxDynamicSharedMemorySize, TG_SMEM_BYTES);

    static cudaStream_t s2 = nullptr;
    static cudaEvent_t evFork = nullptr, evJoin = nullptr, evGather = nullptr;
    if (s2 == nullptr) {
        cudaStreamCreateWithFlags(&s2, cudaStreamNonBlocking);
        cudaEventCreateWithFlags(&evFork, cudaEventDisableTiming);
        cudaEventCreateWithFlags(&evJoin, cudaEventDisableTiming);
        cudaEventCreateWithFlags(&evGather, cudaEventDisableTiming);
    }
    bool fork = (s2 != nullptr && evFork != nullptr && evJoin != nullptr && evGather != nullptr);
    cudaStream_t sg = fork ? s2 : (cudaStream_t)0;

    cudaMemsetAsync(p_ccnt, 0, NCELL * sizeof(int));
    cudaMemsetAsync(p_pcnt, 0, NCELL * sizeof(int));

    if (fork) {
        cudaEventRecord(evFork, 0);
        cudaStreamWaitEvent(s2, evFork, 0);
    }

    int nblk = (N + 127) / 128;

    // ---- branch B (s2): K/V projections on tensor cores, then Wq ----
    tgemm_kernel<0><<<nblk, 256, TG_SMEM_BYTES, sg>>>(feats, Wk, nullptr, p_kall, nullptr, N);
    tgemm_kernel<0><<<nblk, 256, TG_SMEM_BYTES, sg>>>(feats, Wv, nullptr, p_vall, nullptr, N);

    // ---- branch A (default): gather + binning + sorted point scan ----
    gather_kernel<<<(M * DIMC + 255) / 256, 256>>>(xyz, feats, idxc, M);
    if (fork) {
        cudaEventRecord(evGather, 0);
        cudaStreamWaitEvent(s2, evGather, 0);
    }
    gemm32_kernel<false, false><<<dim3((M + 31) / 32, 1), 256, 0, sg>>>(
        p_cfeat, Wq, nullptr, p_q, M, 128, 128);

    bin_count_kernel<<<(M + 255) / 256, 256>>>(M);
    scan_cells_kernel<<<1, 1024>>>(p_ccnt, p_cstart, p_cptr, NCELL);
    bin_scatter_kernel<<<(M + 255) / 256, 256>>>(M);
    point_cell_kernel<<<(N + 255) / 256, 256>>>(xyz, N);
    scan_cells_kernel<<<1, 1024>>>(p_pcnt, p_pstart, p_pptr, NCELL);
    point_scatter_kernel<<<(N + 255) / 256, 256>>>(xyz, N);
    point_scan_kernel<<<(N + 255) / 256, 256>>>(N);
    select_topk_kernel<<<M, 128>>>(M);

    if (fork) {
        cudaEventRecord(evJoin, s2);
        cudaStreamWaitEvent(0, evJoin, 0);
    }

    attn_kernel<<<M, 128>>>(M);

    gemm32_kernel<true, false><<<dim3((M + 31) / 32, 1), 256>>>(p_ao, Wo, bo, p_upd, M, 128, 128);
    ln_res_kernel<<<(M + 7) / 8, 256>>>(p_upd, p_cfeat, n1w, n1b, p_cf1, M);
    gemm32_kernel<true, true ><<<dim3((M + 31) / 32, 4), 256>>>(p_cf1, W1, b1, p_hid, M, 128, 512);
    gemm32_kernel<true, false><<<dim3((M + 31) / 32, 1), 256>>>(p_hid, W2, b2, p_ffn, M, 512, 128);
    ln_res_kernel<<<(M + 7) / 8, 256>>>(p_ffn, p_cf1, n2w, n2b, p_cf, M);

    // upsample: interp -> U (g_kall); tensor gemm fused: out = feats + U + relu(U@Wp + bp)
    interp_kernel<<<(N * 32 + 255) / 256, 256>>>(p_kall, N);
    tgemm_kernel<1><<<nblk, 256, TG_SMEM_BYTES>>>(p_kall, Wp, bp, out, feats, N);
}

// round 11
// speedup vs baseline: 1.2140x; 1.2140x over previous
#include <cuda_runtime.h>
#include <math.h>

#define DIMC 128
#define NMAX 50000
#define MMAX 2500
#define CAP  2048
#define MAXK 32
#define KNN  8
#define SCALE 0.17677669529663687f  // 1/sqrt(32)

// spatial grid (coarse: ~0.9 centers/cell, fast shell expansion)
#define GC   14
#define NCELL (GC*GC*GC)          // 2744
#define CELLH 0.9f
#define INVH  1.1111111111111112f
#define ORG  (-6.3f)

// ---------------- scratch (__device__ globals; no allocation allowed) -------
__device__ float4 g_center[MMAX];
__device__ int    g_ccell[MMAX];
__device__ int    g_ccnt[MMAX];
__device__ float  g_cfeat[MMAX * DIMC];
__device__ int    g_cand_idx[MMAX * CAP];
__device__ float  g_cand_dist[MMAX * CAP];
__device__ int    g_nbr_idx[MMAX * MAXK];
__device__ int    g_nbr_cnt[MMAX];
__device__ float  g_q[MMAX * DIMC];
__device__ float  g_attnout[MMAX * DIMC];
__device__ float  g_upd[MMAX * DIMC];
__device__ float  g_cf1[MMAX * DIMC];
__device__ float  g_hid[MMAX * 4 * DIMC];
__device__ float  g_ffn[MMAX * DIMC];
__device__ float  g_cf[MMAX * DIMC];
__device__ float  g_kall[NMAX * DIMC];   // later reused as U (interp output)
__device__ float  g_vall[NMAX * DIMC];
__device__ int    g_knn_idx[NMAX * KNN];
__device__ float  g_knn_dist[NMAX * KNN];
// center binning
__device__ int    g_cellcnt[NCELL];
__device__ int    g_cellstart[NCELL + 1];
__device__ int    g_cellptr[NCELL];
__device__ float4 g_binc[MMAX];
__device__ int    g_binm[MMAX];
// point sorting
__device__ int    g_pcellcnt[NCELL];
__device__ int    g_pcellstart[NCELL + 1];
__device__ int    g_pcellptr[NCELL];
__device__ float4 g_pxyz[NMAX];
__device__ int    g_psort[NMAX];

// ---------------- f32x2 packed-FMA helpers ----------------------------------
__device__ __forceinline__ void fma2(unsigned long long& d, unsigned long long a,
                                     unsigned long long b) {
    asm("fma.rn.f32x2 %0, %1, %2, %0;" : "+l"(d) : "l"(a), "l"(b));
}
__device__ __forceinline__ unsigned long long pack2(float v) {
    unsigned long long r;
    asm("mov.b64 %0, {%1, %1};" : "=l"(r) : "r"(__float_as_uint(v)));
    return r;
}
__device__ __forceinline__ float2 unpack2(unsigned long long a) {
    unsigned int lo, hi;
    asm("mov.b64 {%0, %1}, %2;" : "=r"(lo), "=r"(hi) : "l"(a));
    return make_float2(__uint_as_float(lo), __uint_as_float(hi));
}

// ---------------- gather centers + zero counters ----------------------------
__global__ void gather_kernel(const float* __restrict__ xyz,
                              const float* __restrict__ feats,
                              const int* __restrict__ idxc, int M) {
    int t = blockIdx.x * blockDim.x + threadIdx.x;
    if (t < M) {
        int n = idxc[t];
        float x = xyz[n * 3 + 0], y = xyz[n * 3 + 1], z = xyz[n * 3 + 2];
        g_center[t] = make_float4(x, y, z, x * x + y * y + z * z);
        g_ccnt[t] = 0;
        int ix = min(max((int)floorf((x - ORG) * INVH), 0), GC - 1);
        int iy = min(max((int)floorf((y - ORG) * INVH), 0), GC - 1);
        int iz = min(max((int)floorf((z - ORG) * INVH), 0), GC - 1);
        g_ccell[t] = (iz * GC + iy) * GC + ix;
    }
    if (t < M * DIMC) {
        int m = t >> 7, c = t & 127;
        g_cfeat[t] = feats[idxc[m] * DIMC + c];
    }
}

// ---------------- binning: count / scan / scatter ---------------------------
__global__ void bin_count_kernel(int M) {
    int m = blockIdx.x * blockDim.x + threadIdx.x;
    if (m < M) atomicAdd(&g_cellcnt[g_ccell[m]], 1);
}

__global__ void scan_cells_kernel(const int* __restrict__ cnt, int* __restrict__ start,
                                  int* __restrict__ ptr, int ncell) {
    __shared__ int part[1024];
    int t = threadIdx.x;
    int PER = (ncell + 1023) / 1024;
    int b0 = t * PER, b1 = min(b0 + PER, ncell);
    int s = 0;
    for (int i = b0; i < b1; i++) s += cnt[i];
    part[t] = s;
    __syncthreads();
    for (int off = 1; off < 1024; off <<= 1) {
        int v = (t >= off) ? part[t - off] : 0;
        __syncthreads();
        part[t] += v;
        __syncthreads();
    }
    int run = (t == 0) ? 0 : part[t - 1];
    for (int i = b0; i < b1; i++) {
        int c = cnt[i];
        start[i] = run;
        ptr[i] = run;
        run += c;
    }
    if (t == 1023) start[ncell] = run;
}

__global__ void bin_scatter_kernel(int M) {
    int m = blockIdx.x * blockDim.x + threadIdx.x;
    if (m < M) {
        int slot = atomicAdd(&g_cellptr[g_ccell[m]], 1);
        g_binc[slot] = g_center[m];
        g_binm[slot] = m;
    }
}

// ---------------- point sort by cell ----------------------------------------
__global__ void point_cell_kernel(const float* __restrict__ xyz, int N) {
    int n = blockIdx.x * blockDim.x + threadIdx.x;
    if (n >= N) return;
    float x = xyz[n * 3 + 0], y = xyz[n * 3 + 1], z = xyz[n * 3 + 2];
    int ix = min(max((int)floorf((x - ORG) * INVH), 0), GC - 1);
    int iy = min(max((int)floorf((y - ORG) * INVH), 0), GC - 1);
    int iz = min(max((int)floorf((z - ORG) * INVH), 0), GC - 1);
    atomicAdd(&g_pcellcnt[(iz * GC + iy) * GC + ix], 1);
}

__global__ void point_scatter_kernel(const float* __restrict__ xyz, int N) {
    int n = blockIdx.x * blockDim.x + threadIdx.x;
    if (n >= N) return;
    float x = xyz[n * 3 + 0], y = xyz[n * 3 + 1], z = xyz[n * 3 + 2];
    int ix = min(max((int)floorf((x - ORG) * INVH), 0), GC - 1);
    int iy = min(max((int)floorf((y - ORG) * INVH), 0), GC - 1);
    int iz = min(max((int)floorf((z - ORG) * INVH), 0), GC - 1);
    int slot = atomicAdd(&g_pcellptr[(iz * GC + iy) * GC + ix], 1);
    g_pxyz[slot] = make_float4(x, y, z, x * x + y * y + z * z);
    g_psort[slot] = n;
}

// ---------------- per-cell scan helper ---------------------------------------
template <bool BALL>
__device__ __forceinline__ void scan_cell(int cid, float x, float y, float z, float s,
                                          int n, float kd[KNN], int ki[KNN]) {
    int c0 = g_cellstart[cid], c1 = g_cellstart[cid + 1];
    for (int j = c0; j < c1; j++) {
        float4 c = g_binc[j];
        float dot = c.x * x + c.y * y + c.z * z;
        float d2 = (c.w + s) - 2.0f * dot;
        if (BALL) {
            if (d2 < 0.0900001f) {
                float dist = (d2 > 0.0f) ? sqrtf(d2) : 0.0f;
                if (dist < 0.3f) {
                    int m = g_binm[j];
                    int slot = atomicAdd(&g_ccnt[m], 1);
                    if (slot < CAP) {
                        g_cand_idx[m * CAP + slot] = n;
                        g_cand_dist[m * CAP + slot] = dist;
                    }
                }
            }
        }
        int ni = g_binm[j];
        if (d2 < kd[KNN - 1] || (d2 == kd[KNN - 1] && ni < ki[KNN - 1])) {
            float nd = d2;
#pragma unroll
            for (int i = 0; i < KNN; i++) {
                if (nd < kd[i] || (nd == kd[i] && ni < ki[i])) {
                    float td = kd[i]; int ti = ki[i];
                    kd[i] = nd; ki[i] = ni; nd = td; ni = ti;
                }
            }
        }
    }
}

// ---------------- point scan over SORTED points: ball + exact KNN -----------
__global__ void point_scan_kernel(int N) {
    int t = blockIdx.x * blockDim.x + threadIdx.x;
    if (t >= N) return;
    float4 p = g_pxyz[t];
    int n = g_psort[t];
    float x = p.x, y = p.y, z = p.z, s = p.w;
    int ix = min(max((int)floorf((x - ORG) * INVH), 0), GC - 1);
    int iy = min(max((int)floorf((y - ORG) * INVH), 0), GC - 1);
    int iz = min(max((int)floorf((z - ORG) * INVH), 0), GC - 1);

    float kd[KNN]; int ki[KNN];
#pragma unroll
    for (int i = 0; i < KNN; i++) { kd[i] = 3.0e38f; ki[i] = 0x7fffffff; }

    // R=1 cube: exact ball coverage (cell 0.9 > radius 0.3) + KNN seed
    for (int dz = -1; dz <= 1; dz++) {
        int jz = iz + dz; if (jz < 0 || jz >= GC) continue;
        for (int dy = -1; dy <= 1; dy++) {
            int jy = iy + dy; if (jy < 0 || jy >= GC) continue;
            for (int dx = -1; dx <= 1; dx++) {
                int jx = ix + dx; if (jx < 0 || jx >= GC) continue;
                scan_cell<true>((jz * GC + jy) * GC + jx, x, y, z, s, n, kd, ki);
            }
        }
    }
    // expand shells until 8th-best beats the guaranteed-covered radius
    int R = 1;
    while (true) {
        float rx = fminf(x - (ORG + (ix - R) * CELLH), (ORG + (ix + R + 1) * CELLH) - x);
        float ry = fminf(y - (ORG + (iy - R) * CELLH), (ORG + (iy + R + 1) * CELLH) - y);
        float rz = fminf(z - (ORG + (iz - R) * CELLH), (ORG + (iz + R + 1) * CELLH) - z);
        float rc = fminf(rx, fminf(ry, rz));
        if (rc > 0.0f && kd[KNN - 1] < rc * rc) break;
        if (R >= GC) break;
        R++;
        for (int dz = -R; dz <= R; dz++) {
            int jz = iz + dz; if (jz < 0 || jz >= GC) continue;
            bool zf = (dz == -R) || (dz == R);
            for (int dy = -R; dy <= R; dy++) {
                int jy = iy + dy; if (jy < 0 || jy >= GC) continue;
                bool yf = (dy == -R) || (dy == R);
                if (zf || yf) {
                    for (int dx = -R; dx <= R; dx++) {
                        int jx = ix + dx; if (jx < 0 || jx >= GC) continue;
                        scan_cell<false>((jz * GC + jy) * GC + jx, x, y, z, s, n, kd, ki);
                    }
                } else {
                    int jx = ix - R;
                    if (jx >= 0) scan_cell<false>((jz * GC + jy) * GC + jx, x, y, z, s, n, kd, ki);
                    jx = ix + R;
                    if (jx < GC) scan_cell<false>((jz * GC + jy) * GC + jx, x, y, z, s, n, kd, ki);
                }
            }
        }
    }
#pragma unroll
    for (int i = 0; i < KNN; i++) {
        float d2 = kd[i];
        g_knn_idx[n * KNN + i] = ki[i];
        g_knn_dist[n * KNN + i] = (d2 > 0.0f) ? sqrtf(d2) : 0.0f;
    }
}

// ---------------- per-center top-32 selection (stable ties by index) --------
__global__ void select_topk_kernel(int M) {
    int m = blockIdx.x;
    int tid = threadIdx.x;  // 128
    __shared__ float sd[CAP];
    __shared__ int   si[CAP];
    __shared__ float rd[128];
    __shared__ int   ri[128];
    __shared__ int   rp[128];
    int cnt = g_ccnt[m];
    if (cnt > CAP) cnt = CAP;
    for (int i = tid; i < cnt; i += blockDim.x) {
        sd[i] = g_cand_dist[m * CAP + i];
        si[i] = g_cand_idx[m * CAP + i];
    }
    __syncthreads();
    for (int r = 0; r < MAXK; r++) {
        float bd = 3.0e38f; int bi = 0x7fffffff; int bp = -1;
        for (int i = tid; i < cnt; i += blockDim.x) {
            float dd = sd[i]; int ii = si[i];
            if (dd < bd || (dd == bd && ii < bi)) { bd = dd; bi = ii; bp = i; }
        }
        rd[tid] = bd; ri[tid] = bi; rp[tid] = bp;
        __syncthreads();
        for (int st = 64; st > 0; st >>= 1) {
            if (tid < st) {
                if (rd[tid + st] < rd[tid] ||
                    (rd[tid + st] == rd[tid] && ri[tid + st] < ri[tid])) {
                    rd[tid] = rd[tid + st]; ri[tid] = ri[tid + st]; rp[tid] = rp[tid + st];
                }
            }
            __syncthreads();
        }
        if (tid == 0) {
            g_nbr_idx[m * MAXK + r] = (r < cnt) ? ri[0] : -1;
            if (rp[0] >= 0) sd[rp[0]] = 3.0e38f;
        }
        __syncthreads();
    }
    if (tid == 0) g_nbr_cnt[m] = (cnt < MAXK) ? cnt : MAXK;
}

// ---------------- fp32 tiled GEMM 128x128 tile, f32x2 FMAs, prefetch --------
// FINAL: C = F + A + relu(acc + bias)   (fused upsample tail)
template <bool BIAS, bool RELU, bool FINAL>
__global__ void gemm128_kernel(const float* __restrict__ A, const float* __restrict__ B,
                               const float* __restrict__ bias, float* __restrict__ C,
                               const float* __restrict__ F,
                               int Mr, int K, int Nc) {
    __shared__ float As[8][128];
    __shared__ float Bs[8][128];
    int bm = blockIdx.x * 128;
    int bn = blockIdx.y * 128;
    int tid = threadIdx.x;
    int ty = tid >> 4, tx = tid & 15;
    unsigned long long acc2[8][4];
#pragma unroll
    for (int i = 0; i < 8; i++)
#pragma unroll
        for (int j = 0; j < 4; j++) acc2[i][j] = 0ull;

    int arow = tid >> 1, akc = (tid & 1) * 4;
    int brow = tid >> 5, bcol = (tid & 31) * 4;
    bool aok = (bm + arow < Mr);
    const float* aptr = &A[(size_t)(bm + arow) * K + akc];
    const float* bptr = &B[(size_t)brow * Nc + bn + bcol];

    float4 av = aok ? *(const float4*)aptr : make_float4(0.f, 0.f, 0.f, 0.f);
    float4 bv = *(const float4*)bptr;

    for (int k0 = 0; k0 < K; k0 += 8) {
        As[akc + 0][arow] = av.x; As[akc + 1][arow] = av.y;
        As[akc + 2][arow] = av.z; As[akc + 3][arow] = av.w;
        *(float4*)&Bs[brow][bcol] = bv;
        __syncthreads();
        if (k0 + 8 < K) {  // prefetch next slab while computing
            av = aok ? *(const float4*)(aptr + k0 + 8) : make_float4(0.f, 0.f, 0.f, 0.f);
            bv = *(const float4*)(bptr + (size_t)(k0 + 8) * Nc);
        }
#pragma unroll
        for (int kk = 0; kk < 8; kk++) {
            float a[8];
            *(float4*)(a)     = *(float4*)&As[kk][ty * 8];
            *(float4*)(a + 4) = *(float4*)&As[kk][ty * 8 + 4];
            ulonglong2 bq0 = *(const ulonglong2*)&Bs[kk][tx * 8];
            ulonglong2 bq1 = *(const ulonglong2*)&Bs[kk][tx * 8 + 4];
#pragma unroll
            for (int i = 0; i < 8; i++) {
                unsigned long long ai = pack2(a[i]);
                fma2(acc2[i][0], ai, bq0.x);
                fma2(acc2[i][1], ai, bq0.y);
                fma2(acc2[i][2], ai, bq1.x);
                fma2(acc2[i][3], ai, bq1.y);
            }
        }
        __syncthreads();
    }
#pragma unroll
    for (int i = 0; i < 8; i++) {
        int r = bm + ty * 8 + i;
        if (r < Mr) {
#pragma unroll
            for (int jq = 0; jq < 2; jq++) {
                int c = bn + tx * 8 + jq * 4;
                float2 v0 = unpack2(acc2[i][jq * 2 + 0]);
                float2 v1 = unpack2(acc2[i][jq * 2 + 1]);
                float4 v = make_float4(v0.x, v0.y, v1.x, v1.y);
                if (BIAS) { v.x += bias[c]; v.y += bias[c + 1]; v.z += bias[c + 2]; v.w += bias[c + 3]; }
                if (RELU) {
                    v.x = fmaxf(v.x, 0.f); v.y = fmaxf(v.y, 0.f);
                    v.z = fmaxf(v.z, 0.f); v.w = fmaxf(v.w, 0.f);
                }
                if (FINAL) {
                    float4 f = *(const float4*)&F[(size_t)r * Nc + c];
                    float4 u = *(const float4*)&A[(size_t)r * Nc + c];
                    v.x += f.x + u.x; v.y += f.y + u.y;
                    v.z += f.z + u.z; v.w += f.w + u.w;
                }
                *(float4*)&C[(size_t)r * Nc + c] = v;
            }
        }
    }
}

// ---------------- fp32 tiled GEMM 32x128 tile (small M), prefetch -----------
template <bool BIAS, bool RELU>
__global__ void gemm32_kernel(const float* __restrict__ A, const float* __restrict__ B,
                              const float* __restrict__ bias, float* __restrict__ C,
                              int Mr, int K, int Nc) {
    __shared__ float As[8][33];
    __shared__ float Bs[8][128];
    int bm = blockIdx.x * 32;
    int bn = blockIdx.y * 128;
    int tid = threadIdx.x;
    int ty = tid >> 5, tx = tid & 31;
    unsigned long long acc2[4][2];
#pragma unroll
    for (int i = 0; i < 4; i++) { acc2[i][0] = 0ull; acc2[i][1] = 0ull; }

    int arow = tid >> 3, acol = tid & 7;
    int brow = tid >> 5, bcol = (tid & 31) * 4;
    bool aok = (bm + arow < Mr);
    const float* aptr = &A[(size_t)(bm + arow) * K + acol];
    const float* bptr = &B[(size_t)brow * Nc + bn + bcol];

    float av = aok ? *aptr : 0.f;
    float4 bv = *(const float4*)bptr;

    for (int k0 = 0; k0 < K; k0 += 8) {
        As[acol][arow] = av;
        *(float4*)&Bs[brow][bcol] = bv;
        __syncthreads();
        if (k0 + 8 < K) {
            av = aok ? *(aptr + k0 + 8) : 0.f;
            bv = *(const float4*)(bptr + (size_t)(k0 + 8) * Nc);
        }
#pragma unroll
        for (int kk = 0; kk < 8; kk++) {
            ulonglong2 bq = *(const ulonglong2*)&Bs[kk][tx * 4];
#pragma unroll
            for (int i = 0; i < 4; i++) {
                unsigned long long ai = pack2(As[kk][ty * 4 + i]);
                fma2(acc2[i][0], ai, bq.x);
                fma2(acc2[i][1], ai, bq.y);
            }
        }
        __syncthreads();
    }
#pragma unroll
    for (int i = 0; i < 4; i++) {
        int r = bm + ty * 4 + i;
        if (r < Mr) {
            int c = bn + tx * 4;
            float2 v0 = unpack2(acc2[i][0]);
            float2 v1 = unpack2(acc2[i][1]);
            float4 v = make_float4(v0.x, v0.y, v1.x, v1.y);
            if (BIAS) { v.x += bias[c]; v.y += bias[c + 1]; v.z += bias[c + 2]; v.w += bias[c + 3]; }
            if (RELU) {
                v.x = fmaxf(v.x, 0.f); v.y = fmaxf(v.y, 0.f);
                v.z = fmaxf(v.z, 0.f); v.w = fmaxf(v.w, 0.f);
            }
            *(float4*)&C[(size_t)r * Nc + c] = v;
        }
    }
}

// ---------------- per-center masked attention -------------------------------
__global__ void attn_kernel(int M) {
    int m = blockIdx.x;
    int t = threadIdx.x;  // 128 threads
    __shared__ float kb[MAXK * 129];
    __shared__ float vb[MAXK * 129];
    __shared__ float qs[128];
    __shared__ float at[128];
    __shared__ int   sidx[MAXK];
    int cnt = g_nbr_cnt[m];
    if (t < MAXK) sidx[t] = g_nbr_idx[m * MAXK + t];
    qs[t] = g_q[m * DIMC + t] * SCALE;
    __syncthreads();
    for (int j = 0; j < cnt; j++) {
        int idx = sidx[j];
        kb[j * 129 + t] = g_kall[(size_t)idx * DIMC + t];
        vb[j * 129 + t] = g_vall[(size_t)idx * DIMC + t];
    }
    __syncthreads();
    int h = t >> 5, j = t & 31;
    float sc;
    if (j < cnt) {
        const float* kr = &kb[j * 129 + h * 32];
        const float* qq = &qs[h * 32];
        float s = 0.f;
#pragma unroll
        for (int d = 0; d < 32; d++) s += qq[d] * kr[d];
        sc = s;
    } else {
        sc = -1e9f;
    }
    float mx = sc;
#pragma unroll
    for (int o = 16; o; o >>= 1) mx = fmaxf(mx, __shfl_xor_sync(0xffffffffu, mx, o));
    float e = expf(sc - mx);
    float sm = e;
#pragma unroll
    for (int o = 16; o; o >>= 1) sm += __shfl_xor_sync(0xffffffffu, sm, o);
    at[t] = e / sm;
    __syncthreads();
    int h2 = t & 3, d2 = t >> 2;
    float o = 0.f;
    for (int jj = 0; jj < cnt; jj++) o += at[h2 * 32 + jj] * vb[jj * 129 + h2 * 32 + d2];
    g_attnout[m * DIMC + t] = o;
}

// ---------------- LayerNorm + residual --------------------------------------
__global__ void ln_res_kernel(const float* __restrict__ x, const float* __restrict__ resid,
                              const float* __restrict__ w, const float* __restrict__ b,
                              float* __restrict__ out, int Mr) {
    int row = blockIdx.x * 8 + (threadIdx.x >> 5);
    int lane = threadIdx.x & 31;
    if (row >= Mr) return;
    const float* xr = x + (size_t)row * DIMC;
    float v[4];
#pragma unroll
    for (int i = 0; i < 4; i++) v[i] = xr[lane + 32 * i];
    float s = v[0] + v[1] + v[2] + v[3];
#pragma unroll
    for (int o = 16; o; o >>= 1) s += __shfl_xor_sync(0xffffffffu, s, o);
    float mu = s * 0.0078125f;
    float s2 = 0.f;
#pragma unroll
    for (int i = 0; i < 4; i++) { float d = v[i] - mu; s2 += d * d; }
#pragma unroll
    for (int o = 16; o; o >>= 1) s2 += __shfl_xor_sync(0xffffffffu, s2, o);
    float r = rsqrtf(s2 * 0.0078125f + 1e-5f);
    const float* rr = resid + (size_t)row * DIMC;
    float* orow = out + (size_t)row * DIMC;
#pragma unroll
    for (int i = 0; i < 4; i++) {
        int c = lane + 32 * i;
        orow[c] = rr[c] + (v[i] - mu) * r * w[c] + b[c];
    }
}

// ---------------- KNN inverse-distance interpolation ------------------------
__global__ void interp_kernel(float* __restrict__ U, int N) {
    int gt = blockIdx.x * blockDim.x + threadIdx.x;
    int p = gt >> 5, lane = gt & 31;
    if (p >= N) return;
    float w[KNN]; int id[KNN];
    float wsum = 0.f;
#pragma unroll
    for (int k = 0; k < KNN; k++) {
        id[k] = g_knn_idx[p * KNN + k];
        float d = g_knn_dist[p * KNN + k] + 1e-6f;
        w[k] = 1.0f / (d * d);
        wsum += w[k];
    }
    float inv = 1.0f / wsum;
    float4 acc = make_float4(0.f, 0.f, 0.f, 0.f);
#pragma unroll
    for (int k = 0; k < KNN; k++) {
        float4 v = *(const float4*)&g_cf[(size_t)id[k] * DIMC + lane * 4];
        acc.x += w[k] * v.x; acc.y += w[k] * v.y;
        acc.z += w[k] * v.z; acc.w += w[k] * v.w;
    }
    acc.x *= inv; acc.y *= inv; acc.z *= inv; acc.w *= inv;
    *(float4*)&U[(size_t)p * DIMC + lane * 4] = acc;
}

// ---------------- host launch ------------------------------------------------
static float* symf(const void* sym) { void* p = nullptr; cudaGetSymbolAddress(&p, sym); return (float*)p; }
static int*   symi(const void* sym) { void* p = nullptr; cudaGetSymbolAddress(&p, sym); return (int*)p; }

extern "C" void kernel_launch(void* const* d_in, const int* in_sizes, int n_in,
                              void* d_out, int out_size) {
    const float* xyz  = (const float*)d_in[0];
    const float* feats= (const float*)d_in[1];
    const float* Wq   = (const float*)d_in[2];
    const float* Wk   = (const float*)d_in[3];
    const float* Wv   = (const float*)d_in[4];
    const float* Wo   = (const float*)d_in[5];
    const float* bo   = (const float*)d_in[6];
    const float* n1w  = (const float*)d_in[7];
    const float* n1b  = (const float*)d_in[8];
    const float* n2w  = (const float*)d_in[9];
    const float* n2b  = (const float*)d_in[10];
    const float* W1   = (const float*)d_in[11];
    const float* b1   = (const float*)d_in[12];
    const float* W2   = (const float*)d_in[13];
    const float* b2   = (const float*)d_in[14];
    const float* Wp   = (const float*)d_in[15];
    const float* bp   = (const float*)d_in[16];
    const int* idxc   = (const int*)d_in[17];
    float* out = (float*)d_out;

    int N = in_sizes[0] / 3;
    int M = in_sizes[17];

    float* p_cfeat = symf(g_cfeat);
    float* p_q     = symf(g_q);
    float* p_kall  = symf(g_kall);
    float* p_vall  = symf(g_vall);
    float* p_ao    = symf(g_attnout);
    float* p_upd   = symf(g_upd);
    float* p_cf1   = symf(g_cf1);
    float* p_hid   = symf(g_hid);
    float* p_ffn   = symf(g_ffn);
    float* p_cf    = symf(g_cf);
    int*   p_ccnt  = symi(g_cellcnt);
    int*   p_cstart= symi(g_cellstart);
    int*   p_cptr  = symi(g_cellptr);
    int*   p_pcnt  = symi(g_pcellcnt);
    int*   p_pstart= symi(g_pcellstart);
    int*   p_pptr  = symi(g_pcellptr);

    static cudaStream_t s2 = nullptr;
    static cudaEvent_t evFork = nullptr, evJoin = nullptr, evGather = nullptr;
    if (s2 == nullptr) {
        cudaStreamCreateWithFlags(&s2, cudaStreamNonBlocking);
        cudaEventCreateWithFlags(&evFork, cudaEventDisableTiming);
        cudaEventCreateWithFlags(&evJoin, cudaEventDisableTiming);
        cudaEventCreateWithFlags(&evGather, cudaEventDisableTiming);
    }
    bool fork = (s2 != nullptr && evFork != nullptr && evJoin != nullptr && evGather != nullptr);
    cudaStream_t sg = fork ? s2 : (cudaStream_t)0;

    cudaMemsetAsync(p_ccnt, 0, NCELL * sizeof(int));
    cudaMemsetAsync(p_pcnt, 0, NCELL * sizeof(int));

    if (fork) {
        cudaEventRecord(evFork, 0);
        cudaStreamWaitEvent(s2, evFork, 0);
    }

    int nblk = (N + 127) / 128;

    // ---- branch B (s2): K/V projections, then Wq after gather ----
    gemm128_kernel<false, false, false><<<dim3(nblk, 1), 256, 0, sg>>>(
        feats, Wk, nullptr, p_kall, nullptr, N, 128, 128);
    gemm128_kernel<false, false, false><<<dim3(nblk, 1), 256, 0, sg>>>(
        feats, Wv, nullptr, p_vall, nullptr, N, 128, 128);

    // ---- branch A (default): gather + binning + sorted point scan ----
    gather_kernel<<<(M * DIMC + 255) / 256, 256>>>(xyz, feats, idxc, M);
    if (fork) {
        cudaEventRecord(evGather, 0);
        cudaStreamWaitEvent(s2, evGather, 0);
    }
    gemm32_kernel<false, false><<<dim3((M + 31) / 32, 1), 256, 0, sg>>>(
        p_cfeat, Wq, nullptr, p_q, M, 128, 128);

    bin_count_kernel<<<(M + 255) / 256, 256>>>(M);
    scan_cells_kernel<<<1, 1024>>>(p_ccnt, p_cstart, p_cptr, NCELL);
    bin_scatter_kernel<<<(M + 255) / 256, 256>>>(M);
    point_cell_kernel<<<(N + 255) / 256, 256>>>(xyz, N);
    scan_cells_kernel<<<1, 1024>>>(p_pcnt, p_pstart, p_pptr, NCELL);
    point_scatter_kernel<<<(N + 255) / 256, 256>>>(xyz, N);
    point_scan_kernel<<<(N + 255) / 256, 256>>>(N);
    select_topk_kernel<<<M, 128>>>(M);

    if (fork) {
        cudaEventRecord(evJoin, s2);
        cudaStreamWaitEvent(0, evJoin, 0);
    }

    attn_kernel<<<M, 128>>>(M);

    gemm32_kernel<true, false><<<dim3((M + 31) / 32, 1), 256>>>(p_ao, Wo, bo, p_upd, M, 128, 128);
    ln_res_kernel<<<(M + 7) / 8, 256>>>(p_upd, p_cfeat, n1w, n1b, p_cf1, M);
    gemm32_kernel<true, true ><<<dim3((M + 31) / 32, 4), 256>>>(p_cf1, W1, b1, p_hid, M, 128, 512);
    gemm32_kernel<true, false><<<dim3((M + 31) / 32, 1), 256>>>(p_hid, W2, b2, p_ffn, M, 512, 128);
    ln_res_kernel<<<(M + 7) / 8, 256>>>(p_ffn, p_cf1, n2w, n2b, p_cf, M);

    // upsample: interp -> U (g_kall); fused gemm: out = feats + U + relu(U@Wp + bp)
    interp_kernel<<<(N * 32 + 255) / 256, 256>>>(p_kall, N);
    gemm128_kernel<true, true, true><<<dim3(nblk, 1), 256>>>(
        p_kall, Wp, bp, out, feats, N, 128, 128);
}

// round 13
// speedup vs baseline: 1.3283x; 1.0941x over previous
#include <cuda_runtime.h>
#include <math.h>

#define DIMC 128
#define NMAX 50000
#define MMAX 2500
#define CAP  2048
#define MAXK 32
#define KNN  8
#define SCALE 0.17677669529663687f  // 1/sqrt(32)

// spatial grid (fine: ~1 center/occupied cell in the Gaussian core)
#define GC   28
#define NCELL (GC*GC*GC)          // 21952
#define CELLH 0.45f
#define INVH  2.2222222222222223f
#define ORG  (-6.3f)

// ---------------- scratch (__device__ globals; no allocation allowed) -------
__device__ float4 g_center[MMAX];
__device__ int    g_ccell[MMAX];
__device__ int    g_ccnt[MMAX];
__device__ float  g_cfeat[MMAX * DIMC];
__device__ int    g_cand_idx[MMAX * CAP];
__device__ float  g_cand_dist[MMAX * CAP];
__device__ int    g_nbr_idx[MMAX * MAXK];
__device__ int    g_nbr_cnt[MMAX];
__device__ float  g_q[MMAX * DIMC];
__device__ float  g_attnout[MMAX * DIMC];
__device__ float  g_upd[MMAX * DIMC];
__device__ float  g_cf1[MMAX * DIMC];
__device__ float  g_hid[MMAX * 4 * DIMC];
__device__ float  g_ffn[MMAX * DIMC];
__device__ float  g_cf[MMAX * DIMC];
__device__ float  g_kall[NMAX * DIMC];   // later reused as U (interp output)
__device__ float  g_vall[NMAX * DIMC];
__device__ int    g_knn_idx[NMAX * KNN];
__device__ float  g_knn_dist[NMAX * KNN];
// center binning
__device__ int    g_cellcnt[NCELL];
__device__ int    g_cellstart[NCELL + 1];
__device__ int    g_cellptr[NCELL];
__device__ float4 g_binc[MMAX];
__device__ int    g_binm[MMAX];
// point sorting
__device__ int    g_pcellcnt[NCELL];
__device__ int    g_pcellstart[NCELL + 1];
__device__ int    g_pcellptr[NCELL];
__device__ float4 g_pxyz[NMAX];
__device__ int    g_psort[NMAX];

// ---------------- f32x2 packed-FMA helpers ----------------------------------
__device__ __forceinline__ void fma2(unsigned long long& d, unsigned long long a,
                                     unsigned long long b) {
    asm("fma.rn.f32x2 %0, %1, %2, %0;" : "+l"(d) : "l"(a), "l"(b));
}
__device__ __forceinline__ unsigned long long pack2(float v) {
    unsigned long long r;
    asm("mov.b64 %0, {%1, %1};" : "=l"(r) : "r"(__float_as_uint(v)));
    return r;
}
__device__ __forceinline__ float2 unpack2(unsigned long long a) {
    unsigned int lo, hi;
    asm("mov.b64 {%0, %1}, %2;" : "=r"(lo), "=r"(hi) : "l"(a));
    return make_float2(__uint_as_float(lo), __uint_as_float(hi));
}

// ---------------- gather centers + zero counters ----------------------------
__global__ void gather_kernel(const float* __restrict__ xyz,
                              const float* __restrict__ feats,
                              const int* __restrict__ idxc, int M) {
    int t = blockIdx.x * blockDim.x + threadIdx.x;
    if (t < M) {
        int n = idxc[t];
        float x = xyz[n * 3 + 0], y = xyz[n * 3 + 1], z = xyz[n * 3 + 2];
        g_center[t] = make_float4(x, y, z, x * x + y * y + z * z);
        g_ccnt[t] = 0;
        int ix = min(max((int)floorf((x - ORG) * INVH), 0), GC - 1);
        int iy = min(max((int)floorf((y - ORG) * INVH), 0), GC - 1);
        int iz = min(max((int)floorf((z - ORG) * INVH), 0), GC - 1);
        g_ccell[t] = (iz * GC + iy) * GC + ix;
    }
    if (t < M * DIMC) {
        int m = t >> 7, c = t & 127;
        g_cfeat[t] = feats[idxc[m] * DIMC + c];
    }
}

// ---------------- binning: count / scan / scatter ---------------------------
__global__ void bin_count_kernel(int M) {
    int m = blockIdx.x * blockDim.x + threadIdx.x;
    if (m < M) atomicAdd(&g_cellcnt[g_ccell[m]], 1);
}

__global__ void scan_cells_kernel(const int* __restrict__ cnt, int* __restrict__ start,
                                  int* __restrict__ ptr, int ncell) {
    __shared__ int part[1024];
    int t = threadIdx.x;
    int PER = (ncell + 1023) / 1024;
    int b0 = t * PER, b1 = min(b0 + PER, ncell);
    int s = 0;
    for (int i = b0; i < b1; i++) s += cnt[i];
    part[t] = s;
    __syncthreads();
    for (int off = 1; off < 1024; off <<= 1) {
        int v = (t >= off) ? part[t - off] : 0;
        __syncthreads();
        part[t] += v;
        __syncthreads();
    }
    int run = (t == 0) ? 0 : part[t - 1];
    for (int i = b0; i < b1; i++) {
        int c = cnt[i];
        start[i] = run;
        ptr[i] = run;
        run += c;
    }
    if (t == 1023) start[ncell] = run;
}

__global__ void bin_scatter_kernel(int M) {
    int m = blockIdx.x * blockDim.x + threadIdx.x;
    if (m < M) {
        int slot = atomicAdd(&g_cellptr[g_ccell[m]], 1);
        g_binc[slot] = g_center[m];
        g_binm[slot] = m;
    }
}

// ---------------- point sort by cell ----------------------------------------
__global__ void point_cell_kernel(const float* __restrict__ xyz, int N) {
    int n = blockIdx.x * blockDim.x + threadIdx.x;
    if (n >= N) return;
    float x = xyz[n * 3 + 0], y = xyz[n * 3 + 1], z = xyz[n * 3 + 2];
    int ix = min(max((int)floorf((x - ORG) * INVH), 0), GC - 1);
    int iy = min(max((int)floorf((y - ORG) * INVH), 0), GC - 1);
    int iz = min(max((int)floorf((z - ORG) * INVH), 0), GC - 1);
    atomicAdd(&g_pcellcnt[(iz * GC + iy) * GC + ix], 1);
}

__global__ void point_scatter_kernel(const float* __restrict__ xyz, int N) {
    int n = blockIdx.x * blockDim.x + threadIdx.x;
    if (n >= N) return;
    float x = xyz[n * 3 + 0], y = xyz[n * 3 + 1], z = xyz[n * 3 + 2];
    int ix = min(max((int)floorf((x - ORG) * INVH), 0), GC - 1);
    int iy = min(max((int)floorf((y - ORG) * INVH), 0), GC - 1);
    int iz = min(max((int)floorf((z - ORG) * INVH), 0), GC - 1);
    int slot = atomicAdd(&g_pcellptr[(iz * GC + iy) * GC + ix], 1);
    g_pxyz[slot] = make_float4(x, y, z, x * x + y * y + z * z);
    g_psort[slot] = n;
}

// ---------------- per-cell scan helper ---------------------------------------
template <bool BALL>
__device__ __forceinline__ void scan_cell(int cid, float x, float y, float z, float s,
                                          int n, float kd[KNN], int ki[KNN]) {
    int c0 = g_cellstart[cid], c1 = g_cellstart[cid + 1];
    for (int j = c0; j < c1; j++) {
        float4 c = g_binc[j];
        float dot = c.x * x + c.y * y + c.z * z;
        float d2 = (c.w + s) - 2.0f * dot;
        if (BALL) {
            if (d2 < 0.0900001f) {
                float dist = (d2 > 0.0f) ? sqrtf(d2) : 0.0f;
                if (dist < 0.3f) {
                    int m = g_binm[j];
                    int slot = atomicAdd(&g_ccnt[m], 1);
                    if (slot < CAP) {
                        g_cand_idx[m * CAP + slot] = n;
                        g_cand_dist[m * CAP + slot] = dist;
                    }
                }
            }
        }
        int ni = g_binm[j];
        if (d2 < kd[KNN - 1] || (d2 == kd[KNN - 1] && ni < ki[KNN - 1])) {
            float nd = d2;
#pragma unroll
            for (int i = 0; i < KNN; i++) {
                if (nd < kd[i] || (nd == kd[i] && ni < ki[i])) {
                    float td = kd[i]; int ti = ki[i];
                    kd[i] = nd; ki[i] = ni; nd = td; ni = ti;
                }
            }
        }
    }
}

// ---------------- point scan over SORTED points: ball + exact KNN -----------
__global__ void point_scan_kernel(int N) {
    int t = blockIdx.x * blockDim.x + threadIdx.x;
    if (t >= N) return;
    float4 p = g_pxyz[t];
    int n = g_psort[t];
    float x = p.x, y = p.y, z = p.z, s = p.w;
    int ix = min(max((int)floorf((x - ORG) * INVH), 0), GC - 1);
    int iy = min(max((int)floorf((y - ORG) * INVH), 0), GC - 1);
    int iz = min(max((int)floorf((z - ORG) * INVH), 0), GC - 1);

    float kd[KNN]; int ki[KNN];
#pragma unroll
    for (int i = 0; i < KNN; i++) { kd[i] = 3.0e38f; ki[i] = 0x7fffffff; }

    // R=1 cube: exact ball coverage (cell 0.45 > radius 0.3) + KNN seed
    for (int dz = -1; dz <= 1; dz++) {
        int jz = iz + dz; if (jz < 0 || jz >= GC) continue;
        for (int dy = -1; dy <= 1; dy++) {
            int jy = iy + dy; if (jy < 0 || jy >= GC) continue;
            for (int dx = -1; dx <= 1; dx++) {
                int jx = ix + dx; if (jx < 0 || jx >= GC) continue;
                scan_cell<true>((jz * GC + jy) * GC + jx, x, y, z, s, n, kd, ki);
            }
        }
    }
    // expand shells until 8th-best beats the guaranteed-covered radius
    int R = 1;
    while (true) {
        float rx = fminf(x - (ORG + (ix - R) * CELLH), (ORG + (ix + R + 1) * CELLH) - x);
        float ry = fminf(y - (ORG + (iy - R) * CELLH), (ORG + (iy + R + 1) * CELLH) - y);
        float rz = fminf(z - (ORG + (iz - R) * CELLH), (ORG + (iz + R + 1) * CELLH) - z);
        float rc = fminf(rx, fminf(ry, rz));
        if (rc > 0.0f && kd[KNN - 1] < rc * rc) break;
        if (R >= GC) break;
        R++;
        for (int dz = -R; dz <= R; dz++) {
            int jz = iz + dz; if (jz < 0 || jz >= GC) continue;
            bool zf = (dz == -R) || (dz == R);
            for (int dy = -R; dy <= R; dy++) {
                int jy = iy + dy; if (jy < 0 || jy >= GC) continue;
                bool yf = (dy == -R) || (dy == R);
                if (zf || yf) {
                    for (int dx = -R; dx <= R; dx++) {
                        int jx = ix + dx; if (jx < 0 || jx >= GC) continue;
                        scan_cell<false>((jz * GC + jy) * GC + jx, x, y, z, s, n, kd, ki);
                    }
                } else {
                    int jx = ix - R;
                    if (jx >= 0) scan_cell<false>((jz * GC + jy) * GC + jx, x, y, z, s, n, kd, ki);
                    jx = ix + R;
                    if (jx < GC) scan_cell<false>((jz * GC + jy) * GC + jx, x, y, z, s, n, kd, ki);
                }
            }
        }
    }
#pragma unroll
    for (int i = 0; i < KNN; i++) {
        float d2 = kd[i];
        g_knn_idx[n * KNN + i] = ki[i];
        g_knn_dist[n * KNN + i] = (d2 > 0.0f) ? sqrtf(d2) : 0.0f;
    }
}

// ---------------- per-center top-32 selection (stable ties by index) --------
__global__ void select_topk_kernel(int M) {
    int m = blockIdx.x;
    int tid = threadIdx.x;  // 128
    __shared__ float sd[CAP];
    __shared__ int   si[CAP];
    __shared__ float rd[128];
    __shared__ int   ri[128];
    __shared__ int   rp[128];
    int cnt = g_ccnt[m];
    if (cnt > CAP) cnt = CAP;
    for (int i = tid; i < cnt; i += blockDim.x) {
        sd[i] = g_cand_dist[m * CAP + i];
        si[i] = g_cand_idx[m * CAP + i];
    }
    __syncthreads();
    for (int r = 0; r < MAXK; r++) {
        float bd = 3.0e38f; int bi = 0x7fffffff; int bp = -1;
        for (int i = tid; i < cnt; i += blockDim.x) {
            float dd = sd[i]; int ii = si[i];
            if (dd < bd || (dd == bd && ii < bi)) { bd = dd; bi = ii; bp = i; }
        }
        rd[tid] = bd; ri[tid] = bi; rp[tid] = bp;
        __syncthreads();
        for (int st = 64; st > 0; st >>= 1) {
            if (tid < st) {
                if (rd[tid + st] < rd[tid] ||
                    (rd[tid + st] == rd[tid] && ri[tid + st] < ri[tid])) {
                    rd[tid] = rd[tid + st]; ri[tid] = ri[tid + st]; rp[tid] = rp[tid + st];
                }
            }
            __syncthreads();
        }
        if (tid == 0) {
            g_nbr_idx[m * MAXK + r] = (r < cnt) ? ri[0] : -1;
            if (rp[0] >= 0) sd[rp[0]] = 3.0e38f;
        }
        __syncthreads();
    }
    if (tid == 0) g_nbr_cnt[m] = (cnt < MAXK) ? cnt : MAXK;
}

// ---------------- fp32 tiled GEMM 128x128 tile, f32x2 FMAs, prefetch --------
// FINAL: C = F + A + relu(acc + bias)   (fused upsample tail)
template <bool BIAS, bool RELU, bool FINAL>
__global__ void gemm128_kernel(const float* __restrict__ A, const float* __restrict__ B,
                               const float* __restrict__ bias, float* __restrict__ C,
                               const float* __restrict__ F,
                               int Mr, int K, int Nc) {
    __shared__ float As[8][128];
    __shared__ float Bs[8][128];
    int bm = blockIdx.x * 128;
    int bn = blockIdx.y * 128;
    int tid = threadIdx.x;
    int ty = tid >> 4, tx = tid & 15;
    unsigned long long acc2[8][4];
#pragma unroll
    for (int i = 0; i < 8; i++)
#pragma unroll
        for (int j = 0; j < 4; j++) acc2[i][j] = 0ull;

    int arow = tid >> 1, akc = (tid & 1) * 4;
    int brow = tid >> 5, bcol = (tid & 31) * 4;
    bool aok = (bm + arow < Mr);
    const float* aptr = &A[(size_t)(bm + arow) * K + akc];
    const float* bptr = &B[(size_t)brow * Nc + bn + bcol];

    float4 av = aok ? *(const float4*)aptr : make_float4(0.f, 0.f, 0.f, 0.f);
    float4 bv = *(const float4*)bptr;

    for (int k0 = 0; k0 < K; k0 += 8) {
        As[akc + 0][arow] = av.x; As[akc + 1][arow] = av.y;
        As[akc + 2][arow] = av.z; As[akc + 3][arow] = av.w;
        *(float4*)&Bs[brow][bcol] = bv;
        __syncthreads();
        if (k0 + 8 < K) {  // prefetch next slab while computing
            av = aok ? *(const float4*)(aptr + k0 + 8) : make_float4(0.f, 0.f, 0.f, 0.f);
            bv = *(const float4*)(bptr + (size_t)(k0 + 8) * Nc);
        }
#pragma unroll
        for (int kk = 0; kk < 8; kk++) {
            float a[8];
            *(float4*)(a)     = *(float4*)&As[kk][ty * 8];
            *(float4*)(a + 4) = *(float4*)&As[kk][ty * 8 + 4];
            ulonglong2 bq0 = *(const ulonglong2*)&Bs[kk][tx * 8];
            ulonglong2 bq1 = *(const ulonglong2*)&Bs[kk][tx * 8 + 4];
#pragma unroll
            for (int i = 0; i < 8; i++) {
                unsigned long long ai = pack2(a[i]);
                fma2(acc2[i][0], ai, bq0.x);
                fma2(acc2[i][1], ai, bq0.y);
                fma2(acc2[i][2], ai, bq1.x);
                fma2(acc2[i][3], ai, bq1.y);
            }
        }
        __syncthreads();
    }
#pragma unroll
    for (int i = 0; i < 8; i++) {
        int r = bm + ty * 8 + i;
        if (r < Mr) {
#pragma unroll
            for (int jq = 0; jq < 2; jq++) {
                int c = bn + tx * 8 + jq * 4;
                float2 v0 = unpack2(acc2[i][jq * 2 + 0]);
                float2 v1 = unpack2(acc2[i][jq * 2 + 1]);
                float4 v = make_float4(v0.x, v0.y, v1.x, v1.y);
                if (BIAS) { v.x += bias[c]; v.y += bias[c + 1]; v.z += bias[c + 2]; v.w += bias[c + 3]; }
                if (RELU) {
                    v.x = fmaxf(v.x, 0.f); v.y = fmaxf(v.y, 0.f);
                    v.z = fmaxf(v.z, 0.f); v.w = fmaxf(v.w, 0.f);
                }
                if (FINAL) {
                    float4 f = *(const float4*)&F[(size_t)r * Nc + c];
                    float4 u = *(const float4*)&A[(size_t)r * Nc + c];
                    v.x += f.x + u.x; v.y += f.y + u.y;
                    v.z += f.z + u.z; v.w += f.w + u.w;
                }
                *(float4*)&C[(size_t)r * Nc + c] = v;
            }
        }
    }
}

// ---------------- fp32 tiled GEMM 32x128 tile (small M), prefetch -----------
template <bool BIAS, bool RELU>
__global__ void gemm32_kernel(const float* __restrict__ A, const float* __restrict__ B,
                              const float* __restrict__ bias, float* __restrict__ C,
                              int Mr, int K, int Nc) {
    __shared__ float As[8][33];
    __shared__ float Bs[8][128];
    int bm = blockIdx.x * 32;
    int bn = blockIdx.y * 128;
    int tid = threadIdx.x;
    int ty = tid >> 5, tx = tid & 31;
    unsigned long long acc2[4][2];
#pragma unroll
    for (int i = 0; i < 4; i++) { acc2[i][0] = 0ull; acc2[i][1] = 0ull; }

    int arow = tid >> 3, acol = tid & 7;
    int brow = tid >> 5, bcol = (tid & 31) * 4;
    bool aok = (bm + arow < Mr);
    const float* aptr = &A[(size_t)(bm + arow) * K + acol];
    const float* bptr = &B[(size_t)brow * Nc + bn + bcol];

    float av = aok ? *aptr : 0.f;
    float4 bv = *(const float4*)bptr;

    for (int k0 = 0; k0 < K; k0 += 8) {
        As[acol][arow] = av;
        *(float4*)&Bs[brow][bcol] = bv;
        __syncthreads();
        if (k0 + 8 < K) {
            av = aok ? *(aptr + k0 + 8) : 0.f;
            bv = *(const float4*)(bptr + (size_t)(k0 + 8) * Nc);
        }
#pragma unroll
        for (int kk = 0; kk < 8; kk++) {
            ulonglong2 bq = *(const ulonglong2*)&Bs[kk][tx * 4];
#pragma unroll
            for (int i = 0; i < 4; i++) {
                unsigned long long ai = pack2(As[kk][ty * 4 + i]);
                fma2(acc2[i][0], ai, bq.x);
                fma2(acc2[i][1], ai, bq.y);
            }
        }
        __syncthreads();
    }
#pragma unroll
    for (int i = 0; i < 4; i++) {
        int r = bm + ty * 4 + i;
        if (r < Mr) {
            int c = bn + tx * 4;
            float2 v0 = unpack2(acc2[i][0]);
            float2 v1 = unpack2(acc2[i][1]);
            float4 v = make_float4(v0.x, v0.y, v1.x, v1.y);
            if (BIAS) { v.x += bias[c]; v.y += bias[c + 1]; v.z += bias[c + 2]; v.w += bias[c + 3]; }
            if (RELU) {
                v.x = fmaxf(v.x, 0.f); v.y = fmaxf(v.y, 0.f);
                v.z = fmaxf(v.z, 0.f); v.w = fmaxf(v.w, 0.f);
            }
            *(float4*)&C[(size_t)r * Nc + c] = v;
        }
    }
}

// ---------------- per-center masked attention -------------------------------
__global__ void attn_kernel(int M) {
    int m = blockIdx.x;
    int t = threadIdx.x;  // 128 threads
    __shared__ float kb[MAXK * 129];
    __shared__ float vb[MAXK * 129];
    __shared__ float qs[128];
    __shared__ float at[128];
    __shared__ int   sidx[MAXK];
    int cnt = g_nbr_cnt[m];
    if (t < MAXK) sidx[t] = g_nbr_idx[m * MAXK + t];
    qs[t] = g_q[m * DIMC + t] * SCALE;
    __syncthreads();
    for (int j = 0; j < cnt; j++) {
        int idx = sidx[j];
        kb[j * 129 + t] = g_kall[(size_t)idx * DIMC + t];
        vb[j * 129 + t] = g_vall[(size_t)idx * DIMC + t];
    }
    __syncthreads();
    int h = t >> 5, j = t & 31;
    float sc;
    if (j < cnt) {
        const float* kr = &kb[j * 129 + h * 32];
        const float* qq = &qs[h * 32];
        float s = 0.f;
#pragma unroll
        for (int d = 0; d < 32; d++) s += qq[d] * kr[d];
        sc = s;
    } else {
        sc = -1e9f;
    }
    float mx = sc;
#pragma unroll
    for (int o = 16; o; o >>= 1) mx = fmaxf(mx, __shfl_xor_sync(0xffffffffu, mx, o));
    float e = expf(sc - mx);
    float sm = e;
#pragma unroll
    for (int o = 16; o; o >>= 1) sm += __shfl_xor_sync(0xffffffffu, sm, o);
    at[t] = e / sm;
    __syncthreads();
    int h2 = t & 3, d2 = t >> 2;
    float o = 0.f;
    for (int jj = 0; jj < cnt; jj++) o += at[h2 * 32 + jj] * vb[jj * 129 + h2 * 32 + d2];
    g_attnout[m * DIMC + t] = o;
}

// ---------------- LayerNorm + residual --------------------------------------
__global__ void ln_res_kernel(const float* __restrict__ x, const float* __restrict__ resid,
                              const float* __restrict__ w, const float* __restrict__ b,
                              float* __restrict__ out, int Mr) {
    int row = blockIdx.x * 8 + (threadIdx.x >> 5);
    int lane = threadIdx.x & 31;
    if (row >= Mr) return;
    const float* xr = x + (size_t)row * DIMC;
    float v[4];
#pragma unroll
    for (int i = 0; i < 4; i++) v[i] = xr[lane + 32 * i];
    float s = v[0] + v[1] + v[2] + v[3];
#pragma unroll
    for (int o = 16; o; o >>= 1) s += __shfl_xor_sync(0xffffffffu, s, o);
    float mu = s * 0.0078125f;
    float s2 = 0.f;
#pragma unroll
    for (int i = 0; i < 4; i++) { float d = v[i] - mu; s2 += d * d; }
#pragma unroll
    for (int o = 16; o; o >>= 1) s2 += __shfl_xor_sync(0xffffffffu, s2, o);
    float r = rsqrtf(s2 * 0.0078125f + 1e-5f);
    const float* rr = resid + (size_t)row * DIMC;
    float* orow = out + (size_t)row * DIMC;
#pragma unroll
    for (int i = 0; i < 4; i++) {
        int c = lane + 32 * i;
        orow[c] = rr[c] + (v[i] - mu) * r * w[c] + b[c];
    }
}

// ---------------- KNN inverse-distance interpolation ------------------------
__global__ void interp_kernel(float* __restrict__ U, int N) {
    int gt = blockIdx.x * blockDim.x + threadIdx.x;
    int p = gt >> 5, lane = gt & 31;
    if (p >= N) return;
    float w[KNN]; int id[KNN];
    float wsum = 0.f;
#pragma unroll
    for (int k = 0; k < KNN; k++) {
        id[k] = g_knn_idx[p * KNN + k];
        float d = g_knn_dist[p * KNN + k] + 1e-6f;
        w[k] = 1.0f / (d * d);
        wsum += w[k];
    }
    float inv = 1.0f / wsum;
    float4 acc = make_float4(0.f, 0.f, 0.f, 0.f);
#pragma unroll
    for (int k = 0; k < KNN; k++) {
        float4 v = *(const float4*)&g_cf[(size_t)id[k] * DIMC + lane * 4];
        acc.x += w[k] * v.x; acc.y += w[k] * v.y;
        acc.z += w[k] * v.z; acc.w += w[k] * v.w;
    }
    acc.x *= inv; acc.y *= inv; acc.z *= inv; acc.w *= inv;
    *(float4*)&U[(size_t)p * DIMC + lane * 4] = acc;
}

// ---------------- host launch ------------------------------------------------
static float* symf(const void* sym) { void* p = nullptr; cudaGetSymbolAddress(&p, sym); return (float*)p; }
static int*   symi(const void* sym) { void* p = nullptr; cudaGetSymbolAddress(&p, sym); return (int*)p; }

extern "C" void kernel_launch(void* const* d_in, const int* in_sizes, int n_in,
                              void* d_out, int out_size) {
    const float* xyz  = (const float*)d_in[0];
    const float* feats= (const float*)d_in[1];
    const float* Wq   = (const float*)d_in[2];
    const float* Wk   = (const float*)d_in[3];
    const float* Wv   = (const float*)d_in[4];
    const float* Wo   = (const float*)d_in[5];
    const float* bo   = (const float*)d_in[6];
    const float* n1w  = (const float*)d_in[7];
    const float* n1b  = (const float*)d_in[8];
    const float* n2w  = (const float*)d_in[9];
    const float* n2b  = (const float*)d_in[10];
    const float* W1   = (const float*)d_in[11];
    const float* b1   = (const float*)d_in[12];
    const float* W2   = (const float*)d_in[13];
    const float* b2   = (const float*)d_in[14];
    const float* Wp   = (const float*)d_in[15];
    const float* bp   = (const float*)d_in[16];
    const int* idxc   = (const int*)d_in[17];
    float* out = (float*)d_out;

    int N = in_sizes[0] / 3;
    int M = in_sizes[17];

    float* p_cfeat = symf(g_cfeat);
    float* p_q     = symf(g_q);
    float* p_kall  = symf(g_kall);
    float* p_vall  = symf(g_vall);
    float* p_ao    = symf(g_attnout);
    float* p_upd   = symf(g_upd);
    float* p_cf1   = symf(g_cf1);
    float* p_hid   = symf(g_hid);
    float* p_ffn   = symf(g_ffn);
    float* p_cf    = symf(g_cf);
    int*   p_ccnt  = symi(g_cellcnt);
    int*   p_cstart= symi(g_cellstart);
    int*   p_cptr  = symi(g_cellptr);
    int*   p_pcnt  = symi(g_pcellcnt);
    int*   p_pstart= symi(g_pcellstart);
    int*   p_pptr  = symi(g_pcellptr);

    static cudaStream_t s2 = nullptr;
    static cudaEvent_t evFork = nullptr, evJoin = nullptr, evGather = nullptr;
    if (s2 == nullptr) {
        cudaStreamCreateWithFlags(&s2, cudaStreamNonBlocking);
        cudaEventCreateWithFlags(&evFork, cudaEventDisableTiming);
        cudaEventCreateWithFlags(&evJoin, cudaEventDisableTiming);
        cudaEventCreateWithFlags(&evGather, cudaEventDisableTiming);
    }
    bool fork = (s2 != nullptr && evFork != nullptr && evJoin != nullptr && evGather != nullptr);
    cudaStream_t sg = fork ? s2 : (cudaStream_t)0;

    cudaMemsetAsync(p_ccnt, 0, NCELL * sizeof(int));
    cudaMemsetAsync(p_pcnt, 0, NCELL * sizeof(int));

    if (fork) {
        cudaEventRecord(evFork, 0);
        cudaStreamWaitEvent(s2, evFork, 0);
    }

    int nblk = (N + 127) / 128;

    // ---- branch B (s2): K/V projections, then Wq after gather ----
    gemm128_kernel<false, false, false><<<dim3(nblk, 1), 256, 0, sg>>>(
        feats, Wk, nullptr, p_kall, nullptr, N, 128, 128);
    gemm128_kernel<false, false, false><<<dim3(nblk, 1), 256, 0, sg>>>(
        feats, Wv, nullptr, p_vall, nullptr, N, 128, 128);

    // ---- branch A (default): gather + binning + sorted point scan ----
    gather_kernel<<<(M * DIMC + 255) / 256, 256>>>(xyz, feats, idxc, M);
    if (fork) {
        cudaEventRecord(evGather, 0);
        cudaStreamWaitEvent(s2, evGather, 0);
    }
    gemm32_kernel<false, false><<<dim3((M + 31) / 32, 1), 256, 0, sg>>>(
        p_cfeat, Wq, nullptr, p_q, M, 128, 128);

    bin_count_kernel<<<(M + 255) / 256, 256>>>(M);
    scan_cells_kernel<<<1, 1024>>>(p_ccnt, p_cstart, p_cptr, NCELL);
    bin_scatter_kernel<<<(M + 255) / 256, 256>>>(M);
    point_cell_kernel<<<(N + 255) / 256, 256>>>(xyz, N);
    scan_cells_kernel<<<1, 1024>>>(p_pcnt, p_pstart, p_pptr, NCELL);
    point_scatter_kernel<<<(N + 255) / 256, 256>>>(xyz, N);
    point_scan_kernel<<<(N + 255) / 256, 256>>>(N);
    select_topk_kernel<<<M, 128>>>(M);

    if (fork) {
        cudaEventRecord(evJoin, s2);
        cudaStreamWaitEvent(0, evJoin, 0);
    }

    attn_kernel<<<M, 128>>>(M);

    gemm32_kernel<true, false><<<dim3((M + 31) / 32, 1), 256>>>(p_ao, Wo, bo, p_upd, M, 128, 128);
    ln_res_kernel<<<(M + 7) / 8, 256>>>(p_upd, p_cfeat, n1w, n1b, p_cf1, M);
    gemm32_kernel<true, true ><<<dim3((M + 31) / 32, 4), 256>>>(p_cf1, W1, b1, p_hid, M, 128, 512);
    gemm32_kernel<true, false><<<dim3((M + 31) / 32, 1), 256>>>(p_hid, W2, b2, p_ffn, M, 512, 128);
    ln_res_kernel<<<(M + 7) / 8, 256>>>(p_ffn, p_cf1, n2w, n2b, p_cf, M);

    // upsample: interp -> U (g_kall); fused gemm: out = feats + U + relu(U@Wp + bp)
    interp_kernel<<<(N * 32 + 255) / 256, 256>>>(p_kall, N);
    gemm128_kernel<true, true, true><<<dim3(nblk, 1), 256>>>(
        p_kall, Wp, bp, out, feats, N, 128, 128);
}